// round 2
// baseline (speedup 1.0000x reference)
#include <cuda_runtime.h>
#include <math.h>

// Problem constants
#define N_    8
#define C_    256
#define H_    128
#define W_    128
#define HW_   (H_*W_)
#define D1_   512
#define D2_   256
#define M_    128    // n*fc*fh*fw
#define L_    4096   // sh*sw = 64*64
#define S_    64     // AH*AW
#define SC_   128    // 2*C/FC
#define HALF_ 64

// ---------------- scratch (device globals: no allocation allowed) ----------------
__device__ float g_y[(size_t)M_ * L_ * SC_];        // (m, l, sc)  268 MB
__device__ float g_wT1[C_ * D1_];                   // proj_w transposed [c][d]
__device__ float g_wT2[C_ * D2_];                   // merge_w transposed [c][d]
__device__ float g_apn[M_ * S_ * HALF_];            // normalized anchor points
__device__ float g_aval[M_ * S_ * HALF_];           // anchor values
__device__ float g_vals[M_ * L_];                   // sigmoid(max)
__device__ int   g_sidx[M_ * L_];                   // argmax anchor (0..63)
__device__ float g_aggn[M_ * S_ * HALF_];           // normalized aggregates
__device__ float g_disp[(size_t)N_ * C_ * HW_];     // disp in NCHW  134 MB

// ---------------- weight transpose: W[d][c] -> WT[c][d] ----------------
template<int DOUT>
__global__ void transpose_kernel(const float* __restrict__ Wm) {
    float* WT = (DOUT == D1_) ? g_wT1 : g_wT2;
    __shared__ float t[32][33];
    int d0 = blockIdx.x * 32, k0 = blockIdx.y * 32;
    for (int i = threadIdx.y; i < 32; i += 8)
        t[i][threadIdx.x] = Wm[(size_t)(d0 + i) * C_ + k0 + threadIdx.x];
    __syncthreads();
    for (int i = threadIdx.y; i < 32; i += 8)
        WT[(size_t)(k0 + i) * DOUT + d0 + threadIdx.x] = t[threadIdx.x][i];
}

// ---------------- 128x128x16 SGEMM over pixels ----------------
template<int DOUT, bool PERM>
__global__ __launch_bounds__(256, 2)
void gemm128_kernel(const float* __restrict__ Xin, const float* __restrict__ bias,
                    float* __restrict__ Yout)
{
    __shared__ float xs[16][128];
    __shared__ float ws[16][128];
    const float* __restrict__ X  = PERM ? Xin : g_disp;
    const float* __restrict__ WT = PERM ? g_wT1 : g_wT2;

    const int row = blockIdx.y;           // n*128 + h
    const int n = row >> 7, h = row & 127;
    const int dbase = blockIdx.x * 128;
    const int tid = threadIdx.x;
    const int tm = tid >> 4, tn = tid & 15;
    const int lr = tid >> 5;              // 0..7
    const int lc = (tid & 31) << 2;       // 0..124

    const float* xb = X + (size_t)n * C_ * HW_ + (size_t)h * W_;
    const float* wb = WT + dbase;

    float acc[8][8];
#pragma unroll
    for (int i = 0; i < 8; i++)
#pragma unroll
        for (int j = 0; j < 8; j++) acc[i][j] = 0.f;

    for (int k0 = 0; k0 < C_; k0 += 16) {
        *(float4*)&xs[lr][lc]     = *(const float4*)&xb[(size_t)(k0 + lr)     * HW_  + lc];
        *(float4*)&xs[lr + 8][lc] = *(const float4*)&xb[(size_t)(k0 + lr + 8) * HW_  + lc];
        *(float4*)&ws[lr][lc]     = *(const float4*)&wb[(size_t)(k0 + lr)     * DOUT + lc];
        *(float4*)&ws[lr + 8][lc] = *(const float4*)&wb[(size_t)(k0 + lr + 8) * DOUT + lc];
        __syncthreads();
#pragma unroll
        for (int kk = 0; kk < 16; kk++) {
            float a[8], b[8];
            *(float4*)&a[0] = *(float4*)&xs[kk][tm * 8];
            *(float4*)&a[4] = *(float4*)&xs[kk][tm * 8 + 4];
            *(float4*)&b[0] = *(float4*)&ws[kk][tn * 8];
            *(float4*)&b[4] = *(float4*)&ws[kk][tn * 8 + 4];
#pragma unroll
            for (int i = 0; i < 8; i++)
#pragma unroll
                for (int j = 0; j < 8; j++)
                    acc[i][j] += a[i] * b[j];
        }
        __syncthreads();
    }

    float bb[8];
#pragma unroll
    for (int j = 0; j < 8; j++) bb[j] = bias[dbase + tn * 8 + j];

    if (PERM) {
        const int fc = dbase >> 7;
        const int fh = h >> 6, shl = h & 63;
#pragma unroll
        for (int i = 0; i < 8; i++) {
            int w = tm * 8 + i;
            int fw = w >> 6, swl = w & 63;
            int m = ((n * 4 + fc) * 2 + fh) * 2 + fw;
            size_t base = ((size_t)m * L_ + (size_t)(shl * 64 + swl)) * SC_ + tn * 8;
            float4 v0 = make_float4(acc[i][0] + bb[0], acc[i][1] + bb[1],
                                    acc[i][2] + bb[2], acc[i][3] + bb[3]);
            float4 v1 = make_float4(acc[i][4] + bb[4], acc[i][5] + bb[5],
                                    acc[i][6] + bb[6], acc[i][7] + bb[7]);
            *(float4*)&g_y[base]     = v0;
            *(float4*)&g_y[base + 4] = v1;
        }
    } else {
#pragma unroll
        for (int j = 0; j < 8; j++) {
            int d = dbase + tn * 8 + j;
            size_t base = ((size_t)n * DOUT + d) * HW_ + (size_t)h * W_ + tm * 8;
            float4 v0 = make_float4(acc[0][j] + bb[j], acc[1][j] + bb[j],
                                    acc[2][j] + bb[j], acc[3][j] + bb[j]);
            float4 v1 = make_float4(acc[4][j] + bb[j], acc[5][j] + bb[j],
                                    acc[6][j] + bb[j], acc[7][j] + bb[j]);
            *(float4*)&Yout[base]     = v0;
            *(float4*)&Yout[base + 4] = v1;
        }
    }
}

// ---------------- anchors: 8x8 mean pool + l2norm of point half ----------------
__global__ void anchor_kernel() {
    const int s = blockIdx.x, m = blockIdx.y, ch = threadIdx.x;  // 128 threads
    const int ah = s >> 3, aw = s & 7;
    const float* yb = g_y + (size_t)m * L_ * SC_ + ch;
    float sum = 0.f;
#pragma unroll
    for (int r = 0; r < 8; r++) {
        int lbase = (ah * 8 + r) * 64 + aw * 8;
#pragma unroll
        for (int q = 0; q < 8; q++)
            sum += yb[(size_t)(lbase + q) * SC_];
    }
    float mean = sum * (1.f / 64.f);
    float sq = (ch < HALF_) ? mean * mean : 0.f;
#pragma unroll
    for (int o = 16; o > 0; o >>= 1) sq += __shfl_xor_sync(0xffffffffu, sq, o);
    __shared__ float ssq[4];
    if ((ch & 31) == 0) ssq[ch >> 5] = sq;
    __syncthreads();
    float tot = ssq[0] + ssq[1];
    float invn = 1.f / fmaxf(sqrtf(tot), 1e-12f);
    if (ch < HALF_) g_apn [((size_t)m * S_ + s) * HALF_ + ch]          = mean * invn;
    else            g_aval[((size_t)m * S_ + s) * HALF_ + (ch - HALF_)] = mean;
}

// ---------------- sims + sigmoid + max/argmax (argmax on POST-sigmoid fp32
// values, first-index tie-break, matching jnp.argmax semantics) ----------------
__global__ __launch_bounds__(256)
void sims_kernel(const float* __restrict__ alphap, const float* __restrict__ betap) {
    __shared__ float ap[64][68];
    __shared__ float xs[64][68];
    const int m = blockIdx.y;
    const int p0 = blockIdx.x * 256;
    const int tid = threadIdx.x;
    const float alpha = alphap[0], beta = betap[0];

    for (int i = tid; i < S_ * HALF_; i += 256)
        ap[i >> 6][i & 63] = g_apn[(size_t)m * S_ * HALF_ + i];

    const int pix = tid >> 2, grp = tid & 3;
    for (int sub = 0; sub < 4; sub++) {
        const int pb = p0 + sub * 64;
        __syncthreads();  // ap ready (1st iter) / previous xs consumers done
        for (int i = tid; i < 64 * 64; i += 256) {
            int pp = i >> 6, cc = i & 63;
            xs[pp][cc] = g_y[((size_t)m * L_ + pb + pp) * SC_ + cc];
        }
        __syncthreads();
        // normalize this pixel's point vector (4 lanes cooperate)
        float ssq = 0.f;
        for (int c = grp; c < 64; c += 4) { float v = xs[pix][c]; ssq += v * v; }
        ssq += __shfl_xor_sync(0xffffffffu, ssq, 1);
        ssq += __shfl_xor_sync(0xffffffffu, ssq, 2);
        float inv = 1.f / fmaxf(sqrtf(ssq), 1e-12f);
        for (int c = grp; c < 64; c += 4) xs[pix][c] *= inv;
        __syncthreads();

        float acc[16];
#pragma unroll
        for (int i = 0; i < 16; i++) acc[i] = 0.f;
#pragma unroll 4
        for (int c = 0; c < 64; c += 4) {
            float4 xv = *(const float4*)&xs[pix][c];
#pragma unroll
            for (int i = 0; i < 16; i++) {
                float4 a4 = *(const float4*)&ap[i * 4 + grp][c];
                acc[i] += xv.x * a4.x + xv.y * a4.y + xv.z * a4.z + xv.w * a4.w;
            }
        }
        // Argmax on fp32 sigmoid values (NOT logits): sigmoid's fp32 rounding
        // collapses near-ties, and jnp.argmax then picks the FIRST index.
        // Strict > over ascending in-lane indices reproduces that; cross-lane
        // ties resolve to the lower index.
        float best = -1.f; int bidx = 0;
#pragma unroll
        for (int i = 0; i < 16; i++) {
            float t  = alpha * acc[i] + beta;
            float sv = 1.0f / (1.0f + expf(-t));
            int sI = i * 4 + grp;                 // ascending within lane
            if (sv > best) { best = sv; bidx = sI; }
        }
#pragma unroll
        for (int o = 1; o < 4; o <<= 1) {
            float ob = __shfl_xor_sync(0xffffffffu, best, o);
            int   oi = __shfl_xor_sync(0xffffffffu, bidx, o);
            if (ob > best || (ob == best && oi < bidx)) { best = ob; bidx = oi; }
        }
        if (grp == 0) {
            g_vals[(size_t)m * L_ + pb + pix] = best;
            g_sidx[(size_t)m * L_ + pb + pix] = bidx;
        }
    }
}

// ---------------- segment sum + normalize ----------------
__global__ __launch_bounds__(256)
void segsum_kernel() {
    __shared__ float agg[64][65];   // [s][0..63]=value sum, [s][64]=count
    const int m = blockIdx.x, tid = threadIdx.x;
    for (int i = tid; i < 64 * 65; i += 256) {
        int s = i / 65, c = i - s * 65;
        agg[s][c] = (c < 64) ? g_aval[((size_t)m * S_ + s) * HALF_ + c] : 1.0f;
    }
    __syncthreads();
    const int cc = tid & 63, pr = tid >> 6;       // 4 pixels / iter, 64 ch lanes
    for (int pb = 0; pb < L_; pb += 4) {
        int p = pb + pr;
        float v = g_vals[(size_t)m * L_ + p];
        int   s = g_sidx[(size_t)m * L_ + p];
        float xv = g_y[((size_t)m * L_ + p) * SC_ + HALF_ + cc];
        atomicAdd(&agg[s][cc], v * xv);
        if (cc == 0) atomicAdd(&agg[s][64], v);
    }
    __syncthreads();
    for (int i = tid; i < S_ * HALF_; i += 256) {
        int s = i >> 6, c = i & 63;
        g_aggn[(size_t)m * S_ * HALF_ + i] = agg[s][c] / agg[s][64];
    }
}

// ---------------- disp scatter into NCHW ----------------
__global__ void disp_kernel() {
    const int m = blockIdx.x, sh = blockIdx.y;
    const int sw = threadIdx.x & 63, cq = threadIdx.x >> 6;
    const int p = sh * 64 + sw;
    float v = g_vals[(size_t)m * L_ + p];
    int   s = g_sidx[(size_t)m * L_ + p];
    const float* arow = &g_aggn[((size_t)m * S_ + s) * HALF_];
    const int fw = m & 1, fh = (m >> 1) & 1, fc = (m >> 2) & 3, n = m >> 4;
    size_t base = ((size_t)n * C_ + fc * HALF_) * HW_
                + (size_t)(fh * 64 + sh) * W_ + fw * 64 + sw;
    for (int c = cq; c < HALF_; c += 4)
        g_disp[base + (size_t)c * HW_] = v * arow[c];
}

// ---------------- launch ----------------
extern "C" void kernel_launch(void* const* d_in, const int* in_sizes, int n_in,
                              void* d_out, int out_size) {
    const float* x       = (const float*)d_in[0];
    const float* proj_w  = (const float*)d_in[1];
    const float* proj_b  = (const float*)d_in[2];
    const float* merge_w = (const float*)d_in[3];
    const float* merge_b = (const float*)d_in[4];
    const float* alpha   = (const float*)d_in[5];
    const float* beta    = (const float*)d_in[6];
    float* out = (float*)d_out;
    (void)in_sizes; (void)n_in; (void)out_size;

    transpose_kernel<D1_><<<dim3(D1_ / 32, C_ / 32), dim3(32, 8)>>>(proj_w);
    transpose_kernel<D2_><<<dim3(D2_ / 32, C_ / 32), dim3(32, 8)>>>(merge_w);

    gemm128_kernel<D1_, true ><<<dim3(4, N_ * H_), 256>>>(x, proj_b, nullptr);
    anchor_kernel<<<dim3(S_, M_), 128>>>();
    sims_kernel<<<dim3(16, M_), 256>>>(alpha, beta);
    segsum_kernel<<<M_, 256>>>();
    disp_kernel<<<dim3(M_, 64), 256>>>();
    gemm128_kernel<D2_, false><<<dim3(2, N_ * H_), 256>>>(nullptr, merge_b, out);
}